// round 12
// baseline (speedup 1.0000x reference)
#include <cuda_runtime.h>
#include <cstdint>

#define BB 32
#define SS 1024
#define II 128
#define HH 128
#define DD 256   // 2*HH

// ---------------- scratch (static device arrays; allocation-free) -------------
__device__ float g_xg[(size_t)2 * BB * SS * 4 * HH];   // [dir][b][s][4H]
__device__ float g_h [(size_t)BB * SS * DD];           // [b][s][2H] (tf32-rounded)
__device__ float g_qk[(size_t)2 * BB * SS * DD];       // q;k tf32-rounded
__device__ float g_v [(size_t)BB * SS * DD];           // vT [b][d][t] tf32-rounded
__device__ float g_sc[(size_t)BB * SS * SS];           // exp(x - m_tile) values
__device__ float2 g_part[(size_t)BB * SS * 8];         // per-row-tile (m, s)
__device__ float  g_fac [(size_t)BB * SS * 8];         // per-row-tile exp(m_j-m)/l
// staged weights for merged launches
__device__ float g_wqk[(size_t)2 * DD * DD];
__device__ float g_wih[(size_t)2 * 4 * HH * II];
__device__ float g_b1 [2 * 4 * HH];
__device__ float g_b2 [2 * 4 * HH];

// ============================ mma.sync tf32 GEMM =============================
// (unchanged from R11 — ldmatrix fragments, flash-factored softmax epilogues)
// =============================================================================
#define GP 36
#define STG_F (128 * GP)
#define STG_B (STG_F * 4)
#define NSTG 3
#define GEMM_SMEM ((2 * NSTG * STG_F + 128 + 1024) * 4)   // 115200 B

__device__ __forceinline__ uint32_t smem_u32(const void* p) {
    uint32_t a;
    asm("{ .reg .u64 t; cvta.to.shared.u64 t, %1; cvt.u32.u64 %0, t; }"
        : "=r"(a) : "l"(p));
    return a;
}
__device__ __forceinline__ void cp16(uint32_t s, const void* g) {
    asm volatile("cp.async.cg.shared.global [%0], [%1], 16;" :: "r"(s), "l"(g));
}
#define CP_COMMIT() asm volatile("cp.async.commit_group;" ::: "memory")
#define CP_WAIT1()  asm volatile("cp.async.wait_group 1;" ::: "memory")
#define CP_WAIT0()  asm volatile("cp.async.wait_group 0;" ::: "memory")

__device__ __forceinline__ uint32_t f2tf(float x) {
    uint32_t r;
    asm("cvt.rna.tf32.f32 %0, %1;" : "=r"(r) : "f"(x));
    return r;
}
__device__ __forceinline__ float roundtf(float x) {
    return __uint_as_float(f2tf(x));
}

__device__ __forceinline__ void ldsm4(uint32_t& r0, uint32_t& r1,
                                      uint32_t& r2, uint32_t& r3,
                                      uint32_t addr) {
    asm volatile("ldmatrix.sync.aligned.m8n8.x4.shared.b16 {%0,%1,%2,%3}, [%4];"
                 : "=r"(r0), "=r"(r1), "=r"(r2), "=r"(r3) : "r"(addr));
}
__device__ __forceinline__ void ldsm2(uint32_t& r0, uint32_t& r1,
                                      uint32_t addr) {
    asm volatile("ldmatrix.sync.aligned.m8n8.x2.shared.b16 {%0,%1}, [%2];"
                 : "=r"(r0), "=r"(r1) : "r"(addr));
}

__device__ __forceinline__ void mma8(float* d, const uint32_t* a,
                                     const uint32_t* b) {
    asm volatile(
        "mma.sync.aligned.m16n8k8.row.col.f32.tf32.tf32.f32 "
        "{%0,%1,%2,%3}, {%4,%5,%6,%7}, {%8,%9}, {%0,%1,%2,%3};"
        : "+f"(d[0]), "+f"(d[1]), "+f"(d[2]), "+f"(d[3])
        : "r"(a[0]), "r"(a[1]), "r"(a[2]), "r"(a[3]), "r"(b[0]), "r"(b[1]));
}

template <bool CVTA, bool CVTB, bool ROUNDC, bool PARTIAL, bool SMAX>
__global__ __launch_bounds__(256, 2) void mma_gemm_nt(
    const float* __restrict__ A, long long sA,
    const float* __restrict__ B, long long sB,
    float* __restrict__ C, long long sC,
    int K, int N, float alpha,
    const float* __restrict__ b1, const float* __restrict__ b2, long long sb,
    float2* __restrict__ part, const float* __restrict__ fac)
{
    extern __shared__ float sm[];
    float* bias   = sm + 2 * NSTG * STG_F;
    float* redm   = bias + 128;            // [128][4]
    float* reds   = redm + 512;            // [128][4]
    const uint32_t smb = smem_u32(sm);

    const int tid  = threadIdx.x;
    const int wid  = tid >> 5, lane = tid & 31;
    const int wm   = wid >> 2, wn = wid & 3;
    const int g    = lane >> 2, tg = lane & 3;

    A += (size_t)blockIdx.z * sA;
    B += (size_t)blockIdx.z * sB;
    C += (size_t)blockIdx.z * sC;
    const int bm = blockIdx.y * 128;
    const int bn = blockIdx.x * 128;

    if (tid < 128) {
        float v = 0.f;
        if (b1) v += b1[blockIdx.z * sb + bn + tid];
        if (b2) v += b2[blockIdx.z * sb + bn + tid];
        bias[tid] = v;
    }

    uint32_t aBase[4], bBase[4];
    {
        const uint32_t a_lane = ((lane & 15) * GP + ((lane >> 4) << 2)) * 4;
        const uint32_t b_lane = ((lane & 7) * GP + (((lane >> 3) & 1) << 2)) * 4;
#pragma unroll
        for (int mt = 0; mt < 4; mt++)
            aBase[mt] = (uint32_t)((wm * 64 + mt * 16) * GP) * 4 + a_lane;
#pragma unroll
        for (int nt = 0; nt < 4; nt++)
            bBase[nt] = (uint32_t)((wn * 32 + nt * 8) * GP) * 4 + b_lane;
    }

    const float* facb = nullptr;
    float facA[4][2], facB[4][2];
    if (SMAX) {
        facb = fac + ((size_t)blockIdx.z * SS + bm) * 8;
#pragma unroll
        for (int mt = 0; mt < 4; mt++) {
            facA[mt][0] = facb[(wm * 64 + mt * 16 + g) * 8];
            facA[mt][1] = facb[(wm * 64 + mt * 16 + g + 8) * 8];
        }
    }

    const int lr = tid >> 3;
    const int c4 = tid & 7;
    const float* Ag0 = A + (size_t)bm * K + c4 * 4;
    const float* Bg0 = B + (size_t)bn * K + c4 * 4;

#define LOADCH(ch, st) do {                                                  \
        const uint32_t abase = smb + (uint32_t)(st) * STG_B;                 \
        const uint32_t bbase = smb + (uint32_t)(NSTG + (st)) * STG_B;        \
        const float* Ac = Ag0 + (ch) * 32;                                   \
        const float* Bc = Bg0 + (ch) * 32;                                   \
        _Pragma("unroll")                                                    \
        for (int i = 0; i < 4; i++) {                                        \
            const int row = lr + 32 * i;                                     \
            const uint32_t off = (uint32_t)(row * GP + c4 * 4) * 4;          \
            cp16(abase + off, Ac + (size_t)row * K);                         \
            cp16(bbase + off, Bc + (size_t)row * K);                         \
        } } while (0)

    float acc[4][4][4];
#pragma unroll
    for (int mt = 0; mt < 4; mt++)
#pragma unroll
        for (int nt = 0; nt < 4; nt++)
#pragma unroll
            for (int e = 0; e < 4; e++) acc[mt][nt][e] = 0.f;

    const int nch = K >> 5;
    LOADCH(0, 0); CP_COMMIT();
    LOADCH(1, 1); CP_COMMIT();

    for (int i = 0; i < nch; i++) {
        const int s = i % 3;
        if (i + 2 < nch) CP_WAIT1(); else CP_WAIT0();
        __syncthreads();
        if (i + 2 < nch) { LOADCH(i + 2, (i + 2) % 3); CP_COMMIT(); }

        if (SMAX && (i & 3) == 0) {
            if (i) {
#pragma unroll
                for (int mt = 0; mt < 4; mt++) {
                    facA[mt][0] = facB[mt][0];
                    facA[mt][1] = facB[mt][1];
                }
            }
            if (i + 4 < nch) {
                const float* fp = facb + (i >> 2) + 1;
#pragma unroll
                for (int mt = 0; mt < 4; mt++) {
                    facB[mt][0] = fp[(wm * 64 + mt * 16 + g) * 8];
                    facB[mt][1] = fp[(wm * 64 + mt * 16 + g + 8) * 8];
                }
            }
        }

        const uint32_t aS = smb + (uint32_t)s * STG_B;
        const uint32_t bS = smb + (uint32_t)(NSTG + s) * STG_B;
#pragma unroll
        for (int ks = 0; ks < 4; ks++) {
            uint32_t af[4][4], bf[4][2];
#pragma unroll
            for (int mt = 0; mt < 4; mt++) {
                ldsm4(af[mt][0], af[mt][1], af[mt][2], af[mt][3],
                      aS + aBase[mt] + ks * 32);
                if (SMAX) {
                    af[mt][0] = f2tf(__uint_as_float(af[mt][0]) * facA[mt][0]);
                    af[mt][1] = f2tf(__uint_as_float(af[mt][1]) * facA[mt][1]);
                    af[mt][2] = f2tf(__uint_as_float(af[mt][2]) * facA[mt][0]);
                    af[mt][3] = f2tf(__uint_as_float(af[mt][3]) * facA[mt][1]);
                } else if (CVTA) {
                    af[mt][0] = f2tf(__uint_as_float(af[mt][0]));
                    af[mt][1] = f2tf(__uint_as_float(af[mt][1]));
                    af[mt][2] = f2tf(__uint_as_float(af[mt][2]));
                    af[mt][3] = f2tf(__uint_as_float(af[mt][3]));
                }
            }
#pragma unroll
            for (int nt = 0; nt < 4; nt++) {
                ldsm2(bf[nt][0], bf[nt][1], bS + bBase[nt] + ks * 32);
                if (CVTB) {
                    bf[nt][0] = f2tf(__uint_as_float(bf[nt][0]));
                    bf[nt][1] = f2tf(__uint_as_float(bf[nt][1]));
                }
            }
#pragma unroll
            for (int mt = 0; mt < 4; mt++)
#pragma unroll
                for (int nt = 0; nt < 4; nt++)
                    mma8(acc[mt][nt], af[mt], bf[nt]);
        }
    }
    __syncthreads();

    if (!PARTIAL) {
#pragma unroll
        for (int mt = 0; mt < 4; mt++) {
            const int r0 = bm + wm * 64 + mt * 16 + g;
#pragma unroll
            for (int nt = 0; nt < 4; nt++) {
                const int cl = wn * 32 + nt * 8 + 2 * tg;
                const int c0 = bn + cl;
                float2 o0, o1;
                o0.x = acc[mt][nt][0] * alpha + bias[cl];
                o0.y = acc[mt][nt][1] * alpha + bias[cl + 1];
                o1.x = acc[mt][nt][2] * alpha + bias[cl];
                o1.y = acc[mt][nt][3] * alpha + bias[cl + 1];
                if (ROUNDC) {
                    o0.x = roundtf(o0.x); o0.y = roundtf(o0.y);
                    o1.x = roundtf(o1.x); o1.y = roundtf(o1.y);
                }
                *(float2*)(C + (size_t)r0 * N + c0)       = o0;
                *(float2*)(C + (size_t)(r0 + 8) * N + c0) = o1;
            }
        }
    } else {
#pragma unroll
        for (int mt = 0; mt < 4; mt++)
#pragma unroll
            for (int h2 = 0; h2 < 2; h2++) {
                float lm = -1e30f;
#pragma unroll
                for (int nt = 0; nt < 4; nt++) {
                    lm = fmaxf(lm, acc[mt][nt][h2 * 2 + 0] * alpha);
                    lm = fmaxf(lm, acc[mt][nt][h2 * 2 + 1] * alpha);
                }
                lm = fmaxf(lm, __shfl_xor_sync(0xffffffffu, lm, 1));
                lm = fmaxf(lm, __shfl_xor_sync(0xffffffffu, lm, 2));
                const int r = wm * 64 + mt * 16 + h2 * 8 + g;
                if (tg == 0) redm[r * 4 + wn] = lm;
            }
        __syncthreads();
#pragma unroll
        for (int mt = 0; mt < 4; mt++)
#pragma unroll
            for (int h2 = 0; h2 < 2; h2++) {
                const int r = wm * 64 + mt * 16 + h2 * 8 + g;
                const float m = fmaxf(fmaxf(redm[r * 4 + 0], redm[r * 4 + 1]),
                                      fmaxf(redm[r * 4 + 2], redm[r * 4 + 3]));
                float* Crow = C + (size_t)(bm + r) * N + bn;
                float ls = 0.f;
#pragma unroll
                for (int nt = 0; nt < 4; nt++) {
                    const int cl = wn * 32 + nt * 8 + 2 * tg;
                    float2 e;
                    e.x = __expf(acc[mt][nt][h2 * 2 + 0] * alpha - m);
                    e.y = __expf(acc[mt][nt][h2 * 2 + 1] * alpha - m);
                    *(float2*)(Crow + cl) = e;
                    ls += e.x + e.y;
                }
                ls += __shfl_xor_sync(0xffffffffu, ls, 1);
                ls += __shfl_xor_sync(0xffffffffu, ls, 2);
                if (tg == 0) reds[r * 4 + wn] = ls;
            }
        __syncthreads();
        if (wn == 0 && tg == 0) {
#pragma unroll
            for (int mt = 0; mt < 4; mt++)
#pragma unroll
                for (int h2 = 0; h2 < 2; h2++) {
                    const int r = wm * 64 + mt * 16 + h2 * 8 + g;
                    const float m = fmaxf(fmaxf(redm[r * 4 + 0], redm[r * 4 + 1]),
                                          fmaxf(redm[r * 4 + 2], redm[r * 4 + 3]));
                    const float s = (reds[r * 4 + 0] + reds[r * 4 + 1]) +
                                    (reds[r * 4 + 2] + reds[r * 4 + 3]);
                    part[((size_t)blockIdx.z * SS + bm + r) * 8 + blockIdx.x] =
                        make_float2(m, s);
                }
        }
    }
#undef LOADCH
}

// =============================================================================
// combine split-softmax partials
// =============================================================================
__global__ __launch_bounds__(256) void softmax_combine(
    const float2* __restrict__ part, float* __restrict__ fac)
{
    const int row = blockIdx.x * 256 + threadIdx.x;
    float2 p[8];
    float m = -1e30f;
#pragma unroll
    for (int j = 0; j < 8; j++) {
        p[j] = part[(size_t)row * 8 + j];
        m = fmaxf(m, p[j].x);
    }
    float l = 0.f;
    float e[8];
#pragma unroll
    for (int j = 0; j < 8; j++) {
        e[j] = __expf(p[j].x - m);
        l += p[j].y * e[j];
    }
    const float inv = 1.f / l;
#pragma unroll
    for (int j = 0; j < 8; j++) fac[(size_t)row * 8 + j] = e[j] * inv;
}

// =============================================================================
// LSTM recurrence — quad gate mapping, 1 barrier/step, double-buffered h.
// thread tid: gate type t = tid&3, hidden unit j = tid>>2, row r = t*128+j.
// Whh row: k 0..95 in regs (48 f32x2), k 96..127 in smem [j4][tid].
// c/h update in-register via 4 quad shfl.idx; branch-free MUFU activations.
// =============================================================================
#define LSTM_SMEM (2 * 128 * 4 + 8 * 512 * 16)   // 66560 B

__device__ __forceinline__ void fma2(unsigned long long& d,
                                     unsigned long long a,
                                     unsigned long long b)
{
    asm("fma.rn.f32x2 %0, %1, %2, %0;" : "+l"(d) : "l"(a), "l"(b));
}
__device__ __forceinline__ void add2(unsigned long long& d,
                                     unsigned long long a)
{
    asm("add.rn.f32x2 %0, %0, %1;" : "+l"(d) : "l"(a));
}
__device__ __forceinline__ float sum2(unsigned long long a)
{
    return __uint_as_float((unsigned)a) + __uint_as_float((unsigned)(a >> 32));
}

__global__ __launch_bounds__(512) void lstm_kernel(
    const float* __restrict__ xg_all,
    const float* __restrict__ Whh_fw,
    const float* __restrict__ Whh_bw,
    float* __restrict__ Hout)
{
    extern __shared__ float sm[];
    float* h_buf = sm;                                 // 2 x 128 (double buffer)
    ulonglong2* w_shq = (ulonglong2*)(sm + 256);       // [j4][tid]: 8*512

    const int dir = blockIdx.x >> 5;
    const int b   = blockIdx.x & 31;
    const int tid = threadIdx.x;
    const int gt  = tid & 3;                 // gate type: 0 i, 1 f, 2 g, 3 o
    const int ju  = tid >> 2;                // hidden unit 0..127
    const int r   = gt * HH + ju;            // gate row in Whh / xg
    const float* Whh = dir ? Whh_bw : Whh_fw;

    // activation constants: sigmoid for i/f/o, tanh = 2*sigmoid(2x)-1 for g
    const float ks = (gt == 2) ? -2.f : -1.f;
    const float ma = (gt == 2) ?  2.f :  1.f;
    const float mb = (gt == 2) ? -1.f :  0.f;

    // register half: k 0..95 (48 f32x2 pairs)
    unsigned long long w2[48];
    {
        const unsigned long long* wr =
            (const unsigned long long*)(Whh + (size_t)r * HH);
#pragma unroll
        for (int i = 0; i < 48; i++) w2[i] = wr[i];
    }
    // smem half: k 96..127 as ulonglong2 [j4][tid]
    {
        const ulonglong2* wsrc =
            (const ulonglong2*)(Whh + (size_t)r * HH + 96);
#pragma unroll
        for (int j4 = 0; j4 < 8; j4++) w_shq[j4 * 512 + tid] = wsrc[j4];
    }
    if (tid < HH) h_buf[tid] = 0.f;          // buffer 0
    float c = 0.f;                           // replicated across the quad
    __syncthreads();

    const float* xg = xg_all + ((size_t)dir * BB + b) * SS * (4 * HH);
    float xg_cur = __ldcs(xg + (size_t)(dir ? SS - 1 : 0) * 512 + r);

    const int lane  = tid & 31;
    const int qbase = lane & ~3;             // quad base lane

    for (int t = 0; t < SS; t++) {
        const int s = dir ? (SS - 1 - t) : t;
        const int cur = t & 1;
        float acc = xg_cur;
        if (t + 1 < SS) {
            const int sn = dir ? (SS - 2 - t) : (t + 1);
            xg_cur = __ldcs(xg + (size_t)sn * 512 + r);
        }

        // dot(h, Whh_row): 4 independent f32x2 chains
        unsigned long long ch0 = 0ull, ch1 = 0ull, ch2 = 0ull, ch3 = 0ull;
        const ulonglong2* hq = (const ulonglong2*)(h_buf + cur * 128);
#pragma unroll
        for (int i = 0; i < 24; i++) {       // k 0..95 (regs)
            ulonglong2 hv = hq[i];
            if (i & 1) { fma2(ch1, w2[2 * i], hv.x); fma2(ch3, w2[2 * i + 1], hv.y); }
            else       { fma2(ch0, w2[2 * i], hv.x); fma2(ch2, w2[2 * i + 1], hv.y); }
        }
#pragma unroll
        for (int j4 = 0; j4 < 8; j4++) {     // k 96..127 (smem)
            ulonglong2 wv = w_shq[j4 * 512 + tid];
            ulonglong2 hv = hq[24 + j4];
            if (j4 & 1) { fma2(ch1, wv.x, hv.x); fma2(ch3, wv.y, hv.y); }
            else        { fma2(ch0, wv.x, hv.x); fma2(ch2, wv.y, hv.y); }
        }
        add2(ch0, ch1); add2(ch2, ch3); add2(ch0, ch2);
        acc += sum2(ch0);

        // branch-free activation (sigmoid / tanh-via-sigmoid)
        const float act =
            fmaf(ma, __fdividef(1.f, 1.f + __expf(ks * acc)), mb);

        // gather quad gates in-register
        const float i_ = __shfl_sync(0xffffffffu, act, qbase + 0, 32);
        const float f_ = __shfl_sync(0xffffffffu, act, qbase + 1, 32);
        const float g_ = __shfl_sync(0xffffffffu, act, qbase + 2, 32);
        const float o_ = __shfl_sync(0xffffffffu, act, qbase + 3, 32);

        c = fmaf(f_, c, i_ * g_);
        const float tc =
            fmaf(2.f, __fdividef(1.f, 1.f + __expf(-2.f * c)), -1.f);
        const float h = o_ * tc;

        if (gt == 0) h_buf[(cur ^ 1) * 128 + ju] = h;
        if (gt == 1)
            Hout[((size_t)b * SS + s) * DD + dir * HH + ju] = roundtf(h);
        __syncthreads();
    }
}

// =============================================================================
// launch
// =============================================================================
extern "C" void kernel_launch(void* const* d_in, const int* in_sizes, int n_in,
                              void* d_out, int out_size)
{
    const float* x     = (const float*)d_in[0];
    const float* fwWih = (const float*)d_in[1];
    const float* fwWhh = (const float*)d_in[2];
    const float* fwbih = (const float*)d_in[3];
    const float* fwbhh = (const float*)d_in[4];
    const float* bwWih = (const float*)d_in[5];
    const float* bwWhh = (const float*)d_in[6];
    const float* bwbih = (const float*)d_in[7];
    const float* bwbhh = (const float*)d_in[8];
    const float* Wq    = (const float*)d_in[9];
    const float* Wk    = (const float*)d_in[10];
    const float* Wv    = (const float*)d_in[11];
    float* out = (float*)d_out;

    float *xg, *h, *qk, *v, *sc, *fac, *wqk, *wih, *b1s, *b2s;
    float2 *part;
    cudaGetSymbolAddress((void**)&xg,   g_xg);
    cudaGetSymbolAddress((void**)&h,    g_h);
    cudaGetSymbolAddress((void**)&qk,   g_qk);
    cudaGetSymbolAddress((void**)&v,    g_v);
    cudaGetSymbolAddress((void**)&sc,   g_sc);
    cudaGetSymbolAddress((void**)&part, g_part);
    cudaGetSymbolAddress((void**)&fac,  g_fac);
    cudaGetSymbolAddress((void**)&wqk,  g_wqk);
    cudaGetSymbolAddress((void**)&wih,  g_wih);
    cudaGetSymbolAddress((void**)&b1s,  g_b1);
    cudaGetSymbolAddress((void**)&b2s,  g_b2);

    cudaFuncSetAttribute(mma_gemm_nt<true, true, false, false, false>,
                         cudaFuncAttributeMaxDynamicSharedMemorySize, GEMM_SMEM);
    cudaFuncSetAttribute(mma_gemm_nt<false, true, true, false, false>,
                         cudaFuncAttributeMaxDynamicSharedMemorySize, GEMM_SMEM);
    cudaFuncSetAttribute(mma_gemm_nt<true, false, true, false, false>,
                         cudaFuncAttributeMaxDynamicSharedMemorySize, GEMM_SMEM);
    cudaFuncSetAttribute(mma_gemm_nt<false, false, false, true, false>,
                         cudaFuncAttributeMaxDynamicSharedMemorySize, GEMM_SMEM);
    cudaFuncSetAttribute(mma_gemm_nt<false, false, false, false, true>,
                         cudaFuncAttributeMaxDynamicSharedMemorySize, GEMM_SMEM);
    cudaFuncSetAttribute(lstm_kernel,
                         cudaFuncAttributeMaxDynamicSharedMemorySize, LSTM_SMEM);

    const long long SD  = (long long)SS * DD;
    const long long SS2 = (long long)SS * SS;
    const long long BSD = (long long)BB * SS * DD;
    const long long WIH = (long long)4 * HH * II;

    cudaMemcpyAsync(wqk,           Wq,    sizeof(float) * DD * DD,
                    cudaMemcpyDeviceToDevice);
    cudaMemcpyAsync(wqk + DD * DD, Wk,    sizeof(float) * DD * DD,
                    cudaMemcpyDeviceToDevice);
    cudaMemcpyAsync(wih,           fwWih, sizeof(float) * WIH,
                    cudaMemcpyDeviceToDevice);
    cudaMemcpyAsync(wih + WIH,     bwWih, sizeof(float) * WIH,
                    cudaMemcpyDeviceToDevice);
    cudaMemcpyAsync(b1s,           fwbih, sizeof(float) * 4 * HH,
                    cudaMemcpyDeviceToDevice);
    cudaMemcpyAsync(b1s + 4 * HH,  bwbih, sizeof(float) * 4 * HH,
                    cudaMemcpyDeviceToDevice);
    cudaMemcpyAsync(b2s,           fwbhh, sizeof(float) * 4 * HH,
                    cudaMemcpyDeviceToDevice);
    cudaMemcpyAsync(b2s + 4 * HH,  bwbhh, sizeof(float) * 4 * HH,
                    cudaMemcpyDeviceToDevice);

    // 1) xg[dir] = x @ Wih[dir]^T + biases (merged fw/bw)
    mma_gemm_nt<true, true, false, false, false>
        <<<dim3(4, 256, 2), 256, GEMM_SMEM>>>(
        x, 0, wih, WIH, xg, (long long)BB * SS * 4 * HH,
        II, 4 * HH, 1.f, b1s, b2s, 4 * HH, nullptr, nullptr);

    // 2) bidirectional LSTM recurrence -> h [B,S,2H]
    lstm_kernel<<<64, 512, LSTM_SMEM>>>(xg, fwWhh, bwWhh, h);

    // 3) q,k projections merged (z=2)
    mma_gemm_nt<false, true, true, false, false>
        <<<dim3(2, 256, 2), 256, GEMM_SMEM>>>(
        h, 0, wqk, (long long)DD * DD, qk, BSD, DD, DD, 1.f,
        nullptr, nullptr, 0, nullptr, nullptr);

    // 3b) vT = Wv @ h^T
    mma_gemm_nt<true, false, true, false, false>
        <<<dim3(8, 2, 32), 256, GEMM_SMEM>>>(
        Wv, 0, h, SD, v, SD, DD, SS, 1.f, nullptr, nullptr, 0,
        nullptr, nullptr);

    // 4) scores: C = exp(q@k^T/16 - m_tile), partials (m_tile, s_tile)
    mma_gemm_nt<false, false, false, true, false>
        <<<dim3(8, 8, 32), 256, GEMM_SMEM>>>(
        qk, SD, qk + BSD, SD, sc, SS2, DD, SS, 0.0625f,
        nullptr, nullptr, 0, part, nullptr);

    // 5) combine partials -> per-(row, tile) factors
    softmax_combine<<<BB * SS / 256, 256>>>(part, fac);

    // 6) out = (exp-values * fac) @ vT^T   (flash-style factored softmax)
    mma_gemm_nt<false, false, false, false, true>
        <<<dim3(2, 8, 32), 256, GEMM_SMEM>>>(
        sc, SS2, v, SD, out, SD, SS, DD, 1.f,
        nullptr, nullptr, 0, nullptr, fac);
}

// round 13
// speedup vs baseline: 1.4933x; 1.4933x over previous
#include <cuda_runtime.h>
#include <cstdint>

#define BB 32
#define SS 1024
#define II 128
#define HH 128
#define DD 256   // 2*HH

// ---------------- scratch (static device arrays; allocation-free) -------------
__device__ float g_xg[(size_t)2 * BB * SS * 4 * HH];   // [dir][b][s][4H]
__device__ float g_h [(size_t)BB * SS * DD];           // [b][s][2H] (tf32-rounded)
__device__ float g_qk[(size_t)2 * BB * SS * DD];       // q;k tf32-rounded
__device__ float g_v [(size_t)BB * SS * DD];           // vT [b][d][t] tf32-rounded
__device__ float g_sc[(size_t)BB * SS * SS];           // exp(x - m_tile) values
__device__ float2 g_part[(size_t)BB * SS * 8];         // per-row-tile (m, s)
__device__ float  g_fac [(size_t)BB * SS * 8];         // per-row-tile exp(m_j-m)/l
// staged weights for merged launches
__device__ float g_wqk[(size_t)2 * DD * DD];
__device__ float g_wih[(size_t)2 * 4 * HH * II];
__device__ float g_b1 [2 * 4 * HH];
__device__ float g_b2 [2 * 4 * HH];

// ============================ mma.sync tf32 GEMM =============================
// (identical to R11 — ldmatrix fragments, flash-factored softmax epilogues)
// =============================================================================
#define GP 36
#define STG_F (128 * GP)
#define STG_B (STG_F * 4)
#define NSTG 3
#define GEMM_SMEM ((2 * NSTG * STG_F + 128 + 1024) * 4)   // 115200 B

__device__ __forceinline__ uint32_t smem_u32(const void* p) {
    uint32_t a;
    asm("{ .reg .u64 t; cvta.to.shared.u64 t, %1; cvt.u32.u64 %0, t; }"
        : "=r"(a) : "l"(p));
    return a;
}
__device__ __forceinline__ void cp16(uint32_t s, const void* g) {
    asm volatile("cp.async.cg.shared.global [%0], [%1], 16;" :: "r"(s), "l"(g));
}
#define CP_COMMIT() asm volatile("cp.async.commit_group;" ::: "memory")
#define CP_WAIT1()  asm volatile("cp.async.wait_group 1;" ::: "memory")
#define CP_WAIT0()  asm volatile("cp.async.wait_group 0;" ::: "memory")

__device__ __forceinline__ uint32_t f2tf(float x) {
    uint32_t r;
    asm("cvt.rna.tf32.f32 %0, %1;" : "=r"(r) : "f"(x));
    return r;
}
__device__ __forceinline__ float roundtf(float x) {
    return __uint_as_float(f2tf(x));
}

__device__ __forceinline__ void ldsm4(uint32_t& r0, uint32_t& r1,
                                      uint32_t& r2, uint32_t& r3,
                                      uint32_t addr) {
    asm volatile("ldmatrix.sync.aligned.m8n8.x4.shared.b16 {%0,%1,%2,%3}, [%4];"
                 : "=r"(r0), "=r"(r1), "=r"(r2), "=r"(r3) : "r"(addr));
}
__device__ __forceinline__ void ldsm2(uint32_t& r0, uint32_t& r1,
                                      uint32_t addr) {
    asm volatile("ldmatrix.sync.aligned.m8n8.x2.shared.b16 {%0,%1}, [%2];"
                 : "=r"(r0), "=r"(r1) : "r"(addr));
}

__device__ __forceinline__ void mma8(float* d, const uint32_t* a,
                                     const uint32_t* b) {
    asm volatile(
        "mma.sync.aligned.m16n8k8.row.col.f32.tf32.tf32.f32 "
        "{%0,%1,%2,%3}, {%4,%5,%6,%7}, {%8,%9}, {%0,%1,%2,%3};"
        : "+f"(d[0]), "+f"(d[1]), "+f"(d[2]), "+f"(d[3])
        : "r"(a[0]), "r"(a[1]), "r"(a[2]), "r"(a[3]), "r"(b[0]), "r"(b[1]));
}

template <bool CVTA, bool CVTB, bool ROUNDC, bool PARTIAL, bool SMAX>
__global__ __launch_bounds__(256, 2) void mma_gemm_nt(
    const float* __restrict__ A, long long sA,
    const float* __restrict__ B, long long sB,
    float* __restrict__ C, long long sC,
    int K, int N, float alpha,
    const float* __restrict__ b1, const float* __restrict__ b2, long long sb,
    float2* __restrict__ part, const float* __restrict__ fac)
{
    extern __shared__ float sm[];
    float* bias   = sm + 2 * NSTG * STG_F;
    float* redm   = bias + 128;            // [128][4]
    float* reds   = redm + 512;            // [128][4]
    const uint32_t smb = smem_u32(sm);

    const int tid  = threadIdx.x;
    const int wid  = tid >> 5, lane = tid & 31;
    const int wm   = wid >> 2, wn = wid & 3;
    const int g    = lane >> 2, tg = lane & 3;

    A += (size_t)blockIdx.z * sA;
    B += (size_t)blockIdx.z * sB;
    C += (size_t)blockIdx.z * sC;
    const int bm = blockIdx.y * 128;
    const int bn = blockIdx.x * 128;

    if (tid < 128) {
        float v = 0.f;
        if (b1) v += b1[blockIdx.z * sb + bn + tid];
        if (b2) v += b2[blockIdx.z * sb + bn + tid];
        bias[tid] = v;
    }

    uint32_t aBase[4], bBase[4];
    {
        const uint32_t a_lane = ((lane & 15) * GP + ((lane >> 4) << 2)) * 4;
        const uint32_t b_lane = ((lane & 7) * GP + (((lane >> 3) & 1) << 2)) * 4;
#pragma unroll
        for (int mt = 0; mt < 4; mt++)
            aBase[mt] = (uint32_t)((wm * 64 + mt * 16) * GP) * 4 + a_lane;
#pragma unroll
        for (int nt = 0; nt < 4; nt++)
            bBase[nt] = (uint32_t)((wn * 32 + nt * 8) * GP) * 4 + b_lane;
    }

    const float* facb = nullptr;
    float facA[4][2], facB[4][2];
    if (SMAX) {
        facb = fac + ((size_t)blockIdx.z * SS + bm) * 8;
#pragma unroll
        for (int mt = 0; mt < 4; mt++) {
            facA[mt][0] = facb[(wm * 64 + mt * 16 + g) * 8];
            facA[mt][1] = facb[(wm * 64 + mt * 16 + g + 8) * 8];
        }
    }

    const int lr = tid >> 3;
    const int c4 = tid & 7;
    const float* Ag0 = A + (size_t)bm * K + c4 * 4;
    const float* Bg0 = B + (size_t)bn * K + c4 * 4;

#define LOADCH(ch, st) do {                                                  \
        const uint32_t abase = smb + (uint32_t)(st) * STG_B;                 \
        const uint32_t bbase = smb + (uint32_t)(NSTG + (st)) * STG_B;        \
        const float* Ac = Ag0 + (ch) * 32;                                   \
        const float* Bc = Bg0 + (ch) * 32;                                   \
        _Pragma("unroll")                                                    \
        for (int i = 0; i < 4; i++) {                                        \
            const int row = lr + 32 * i;                                     \
            const uint32_t off = (uint32_t)(row * GP + c4 * 4) * 4;          \
            cp16(abase + off, Ac + (size_t)row * K);                         \
            cp16(bbase + off, Bc + (size_t)row * K);                         \
        } } while (0)

    float acc[4][4][4];
#pragma unroll
    for (int mt = 0; mt < 4; mt++)
#pragma unroll
        for (int nt = 0; nt < 4; nt++)
#pragma unroll
            for (int e = 0; e < 4; e++) acc[mt][nt][e] = 0.f;

    const int nch = K >> 5;
    LOADCH(0, 0); CP_COMMIT();
    LOADCH(1, 1); CP_COMMIT();

    for (int i = 0; i < nch; i++) {
        const int s = i % 3;
        if (i + 2 < nch) CP_WAIT1(); else CP_WAIT0();
        __syncthreads();
        if (i + 2 < nch) { LOADCH(i + 2, (i + 2) % 3); CP_COMMIT(); }

        if (SMAX && (i & 3) == 0) {
            if (i) {
#pragma unroll
                for (int mt = 0; mt < 4; mt++) {
                    facA[mt][0] = facB[mt][0];
                    facA[mt][1] = facB[mt][1];
                }
            }
            if (i + 4 < nch) {
                const float* fp = facb + (i >> 2) + 1;
#pragma unroll
                for (int mt = 0; mt < 4; mt++) {
                    facB[mt][0] = fp[(wm * 64 + mt * 16 + g) * 8];
                    facB[mt][1] = fp[(wm * 64 + mt * 16 + g + 8) * 8];
                }
            }
        }

        const uint32_t aS = smb + (uint32_t)s * STG_B;
        const uint32_t bS = smb + (uint32_t)(NSTG + s) * STG_B;
#pragma unroll
        for (int ks = 0; ks < 4; ks++) {
            uint32_t af[4][4], bf[4][2];
#pragma unroll
            for (int mt = 0; mt < 4; mt++) {
                ldsm4(af[mt][0], af[mt][1], af[mt][2], af[mt][3],
                      aS + aBase[mt] + ks * 32);
                if (SMAX) {
                    af[mt][0] = f2tf(__uint_as_float(af[mt][0]) * facA[mt][0]);
                    af[mt][1] = f2tf(__uint_as_float(af[mt][1]) * facA[mt][1]);
                    af[mt][2] = f2tf(__uint_as_float(af[mt][2]) * facA[mt][0]);
                    af[mt][3] = f2tf(__uint_as_float(af[mt][3]) * facA[mt][1]);
                } else if (CVTA) {
                    af[mt][0] = f2tf(__uint_as_float(af[mt][0]));
                    af[mt][1] = f2tf(__uint_as_float(af[mt][1]));
                    af[mt][2] = f2tf(__uint_as_float(af[mt][2]));
                    af[mt][3] = f2tf(__uint_as_float(af[mt][3]));
                }
            }
#pragma unroll
            for (int nt = 0; nt < 4; nt++) {
                ldsm2(bf[nt][0], bf[nt][1], bS + bBase[nt] + ks * 32);
                if (CVTB) {
                    bf[nt][0] = f2tf(__uint_as_float(bf[nt][0]));
                    bf[nt][1] = f2tf(__uint_as_float(bf[nt][1]));
                }
            }
#pragma unroll
            for (int mt = 0; mt < 4; mt++)
#pragma unroll
                for (int nt = 0; nt < 4; nt++)
                    mma8(acc[mt][nt], af[mt], bf[nt]);
        }
    }
    __syncthreads();

    if (!PARTIAL) {
#pragma unroll
        for (int mt = 0; mt < 4; mt++) {
            const int r0 = bm + wm * 64 + mt * 16 + g;
#pragma unroll
            for (int nt = 0; nt < 4; nt++) {
                const int cl = wn * 32 + nt * 8 + 2 * tg;
                const int c0 = bn + cl;
                float2 o0, o1;
                o0.x = acc[mt][nt][0] * alpha + bias[cl];
                o0.y = acc[mt][nt][1] * alpha + bias[cl + 1];
                o1.x = acc[mt][nt][2] * alpha + bias[cl];
                o1.y = acc[mt][nt][3] * alpha + bias[cl + 1];
                if (ROUNDC) {
                    o0.x = roundtf(o0.x); o0.y = roundtf(o0.y);
                    o1.x = roundtf(o1.x); o1.y = roundtf(o1.y);
                }
                *(float2*)(C + (size_t)r0 * N + c0)       = o0;
                *(float2*)(C + (size_t)(r0 + 8) * N + c0) = o1;
            }
        }
    } else {
#pragma unroll
        for (int mt = 0; mt < 4; mt++)
#pragma unroll
            for (int h2 = 0; h2 < 2; h2++) {
                float lm = -1e30f;
#pragma unroll
                for (int nt = 0; nt < 4; nt++) {
                    lm = fmaxf(lm, acc[mt][nt][h2 * 2 + 0] * alpha);
                    lm = fmaxf(lm, acc[mt][nt][h2 * 2 + 1] * alpha);
                }
                lm = fmaxf(lm, __shfl_xor_sync(0xffffffffu, lm, 1));
                lm = fmaxf(lm, __shfl_xor_sync(0xffffffffu, lm, 2));
                const int r = wm * 64 + mt * 16 + h2 * 8 + g;
                if (tg == 0) redm[r * 4 + wn] = lm;
            }
        __syncthreads();
#pragma unroll
        for (int mt = 0; mt < 4; mt++)
#pragma unroll
            for (int h2 = 0; h2 < 2; h2++) {
                const int r = wm * 64 + mt * 16 + h2 * 8 + g;
                const float m = fmaxf(fmaxf(redm[r * 4 + 0], redm[r * 4 + 1]),
                                      fmaxf(redm[r * 4 + 2], redm[r * 4 + 3]));
                float* Crow = C + (size_t)(bm + r) * N + bn;
                float ls = 0.f;
#pragma unroll
                for (int nt = 0; nt < 4; nt++) {
                    const int cl = wn * 32 + nt * 8 + 2 * tg;
                    float2 e;
                    e.x = __expf(acc[mt][nt][h2 * 2 + 0] * alpha - m);
                    e.y = __expf(acc[mt][nt][h2 * 2 + 1] * alpha - m);
                    *(float2*)(Crow + cl) = e;
                    ls += e.x + e.y;
                }
                ls += __shfl_xor_sync(0xffffffffu, ls, 1);
                ls += __shfl_xor_sync(0xffffffffu, ls, 2);
                if (tg == 0) reds[r * 4 + wn] = ls;
            }
        __syncthreads();
        if (wn == 0 && tg == 0) {
#pragma unroll
            for (int mt = 0; mt < 4; mt++)
#pragma unroll
                for (int h2 = 0; h2 < 2; h2++) {
                    const int r = wm * 64 + mt * 16 + h2 * 8 + g;
                    const float m = fmaxf(fmaxf(redm[r * 4 + 0], redm[r * 4 + 1]),
                                          fmaxf(redm[r * 4 + 2], redm[r * 4 + 3]));
                    const float s = (reds[r * 4 + 0] + reds[r * 4 + 1]) +
                                    (reds[r * 4 + 2] + reds[r * 4 + 3]);
                    part[((size_t)blockIdx.z * SS + bm + r) * 8 + blockIdx.x] =
                        make_float2(m, s);
                }
        }
    }
#undef LOADCH
}

// =============================================================================
// combine split-softmax partials
// =============================================================================
__global__ __launch_bounds__(256) void softmax_combine(
    const float2* __restrict__ part, float* __restrict__ fac)
{
    const int row = blockIdx.x * 256 + threadIdx.x;
    float2 p[8];
    float m = -1e30f;
#pragma unroll
    for (int j = 0; j < 8; j++) {
        p[j] = part[(size_t)row * 8 + j];
        m = fmaxf(m, p[j].x);
    }
    float l = 0.f;
    float e[8];
#pragma unroll
    for (int j = 0; j < 8; j++) {
        e[j] = __expf(p[j].x - m);
        l += p[j].y * e[j];
    }
    const float inv = 1.f / l;
#pragma unroll
    for (int j = 0; j < 8; j++) fac[(size_t)row * 8 + j] = e[j] * inv;
}

// =============================================================================
// LSTM recurrence — cluster-split: 64 clusters x 2 CTAs x 256 threads.
// CTA rank owns hidden units [rank*64, rank*64+64): all 4 gates (quad map:
// gate type = tid&3, local unit = tid>>2). ALL 128 Whh-row weights in regs.
// Per step: dot over full h (local smem, double-buffered), quad-shfl c/h
// update, h exchanged to peer via st.shared::cluster + mbarrier (arrive AFTER
// __syncthreads so the peer cannot overwrite a buffer still being read).
// =============================================================================
__device__ __forceinline__ void fma2(unsigned long long& d,
                                     unsigned long long a,
                                     unsigned long long b)
{
    asm("fma.rn.f32x2 %0, %1, %2, %0;" : "+l"(d) : "l"(a), "l"(b));
}
__device__ __forceinline__ void add2(unsigned long long& d,
                                     unsigned long long a)
{
    asm("add.rn.f32x2 %0, %0, %1;" : "+l"(d) : "l"(a));
}
__device__ __forceinline__ float sum2(unsigned long long a)
{
    return __uint_as_float((unsigned)a) + __uint_as_float((unsigned)(a >> 32));
}

#define MBAR_WAIT_CLUSTER(mb, ph) do {                                        \
    uint32_t _m = (mb), _p = (ph), _d;                                        \
    asm volatile("{ .reg .pred p;"                                            \
        " mbarrier.try_wait.parity.acquire.cluster.shared::cta.b64 p, [%1], %2;" \
        " selp.b32 %0,1,0,p; }" : "=r"(_d) : "r"(_m), "r"(_p) : "memory");    \
    if (!_d) {                                                                \
        asm volatile("{ .reg .pred P1; WLC_%=: "                              \
            "mbarrier.try_wait.parity.acquire.cluster.shared::cta.b64 P1, [%0], %1, 0x989680;" \
            " @P1 bra.uni WDC_%=; bra.uni WLC_%=; WDC_%=: }"                  \
            :: "r"(_m), "r"(_p) : "memory");                                  \
    } } while (0)

__global__ __launch_bounds__(256, 1) __cluster_dims__(2, 1, 1)
void lstm_kernel(const float* __restrict__ xg_all,
                 const float* __restrict__ Whh_fw,
                 const float* __restrict__ Whh_bw,
                 float* __restrict__ Hout)
{
    __shared__ __align__(16) float h_buf[2][128];
    __shared__ __align__(8) unsigned long long mbar[2];

    const int tid = threadIdx.x;
    uint32_t rank;
    asm("mov.u32 %0, %%cluster_ctarank;" : "=r"(rank));
    const int pair = blockIdx.x >> 1;        // 0..63
    const int dir  = pair >> 5;
    const int b    = pair & 31;
    const int gt   = tid & 3;                // 0 i, 1 f, 2 g, 3 o
    const int ju   = (int)rank * 64 + (tid >> 2);   // global hidden unit
    const int r    = gt * HH + ju;           // gate row in Whh / xg
    const float* Whh = dir ? Whh_bw : Whh_fw;

    // sigmoid for i/f/o; tanh = 2*sigmoid(2x)-1 for g (proven in R12)
    const float ksg = (gt == 2) ? -2.f : -1.f;
    const float ma  = (gt == 2) ?  2.f :  1.f;
    const float mb  = (gt == 2) ? -1.f :  0.f;

    // ENTIRE Whh row in registers (64 f32x2 pairs = 128 regs; cap is 256)
    unsigned long long w2[64];
    {
        const unsigned long long* wr =
            (const unsigned long long*)(Whh + (size_t)r * HH);
#pragma unroll
        for (int i = 0; i < 64; i++) w2[i] = wr[i];
    }

    const uint32_t hb_local = smem_u32(h_buf);
    const uint32_t mb_local = smem_u32(mbar);
    uint32_t hb_rem, mb_rem;
    asm("mapa.shared::cluster.u32 %0, %1, %2;"
        : "=r"(hb_rem) : "r"(hb_local), "r"(rank ^ 1u));
    asm("mapa.shared::cluster.u32 %0, %1, %2;"
        : "=r"(mb_rem) : "r"(mb_local), "r"(rank ^ 1u));

    if (tid < 128) h_buf[0][tid] = 0.f;
    if (tid == 0) {
        asm volatile("mbarrier.init.shared.b64 [%0], 64;" :: "r"(mb_local) : "memory");
        asm volatile("mbarrier.init.shared.b64 [%0], 64;" :: "r"(mb_local + 8) : "memory");
    }
    __syncthreads();
    asm volatile("barrier.cluster.arrive.aligned;" ::: "memory");
    asm volatile("barrier.cluster.wait.aligned;" ::: "memory");

    const float* xg = xg_all + ((size_t)dir * BB + b) * SS * (4 * HH);
    float xg0 = __ldcs(xg + (size_t)(dir ? SS - 1 : 0) * 512 + r);
    float xg1 = __ldcs(xg + (size_t)(dir ? SS - 2 : 1) * 512 + r);

    float c = 0.f;
    const int lane = tid & 31;
    const int qb = lane & ~3;
    int ph0 = 0, ph1 = 0;

    for (int t = 0; t < SS; t++) {
        const int s = dir ? (SS - 1 - t) : t;
        if (t) {   // wait peer's h-half for this step's buffer
            if (t & 1) { MBAR_WAIT_CLUSTER(mb_local + 8, ph1); ph1 ^= 1; }
            else       { MBAR_WAIT_CLUSTER(mb_local,     ph0); ph0 ^= 1; }
        }
        float acc = xg0;
        xg0 = xg1;
        if (t + 2 < SS) {
            const int sn = dir ? (SS - 3 - t) : (t + 2);
            xg1 = __ldcs(xg + (size_t)sn * 512 + r);
        }

        // dot(h, Whh_row): all weights in regs, 4 independent f32x2 chains
        unsigned long long ch0 = 0ull, ch1 = 0ull, ch2 = 0ull, ch3 = 0ull;
        const ulonglong2* hq = (const ulonglong2*)h_buf[t & 1];
#pragma unroll
        for (int i = 0; i < 32; i++) {
            ulonglong2 hv = hq[i];
            if (i & 1) { fma2(ch2, w2[2 * i], hv.x); fma2(ch3, w2[2 * i + 1], hv.y); }
            else       { fma2(ch0, w2[2 * i], hv.x); fma2(ch1, w2[2 * i + 1], hv.y); }
        }
        add2(ch0, ch2); add2(ch1, ch3); add2(ch0, ch1);
        acc += sum2(ch0);

        const float act =
            fmaf(ma, __fdividef(1.f, 1.f + __expf(ksg * acc)), mb);

        const float i_ = __shfl_sync(0xffffffffu, act, qb + 0, 32);
        const float f_ = __shfl_sync(0xffffffffu, act, qb + 1, 32);
        const float g_ = __shfl_sync(0xffffffffu, act, qb + 2, 32);
        const float o_ = __shfl_sync(0xffffffffu, act, qb + 3, 32);

        c = fmaf(f_, c, i_ * g_);
        const float tc =
            fmaf(2.f, __fdividef(1.f, 1.f + __expf(-2.f * c)), -1.f);
        const float h = o_ * tc;

        const int nb = (t + 1) & 1;
        if (gt == 0) {
            h_buf[nb][ju] = h;
            if (t + 1 < SS) {
                asm volatile("st.shared::cluster.f32 [%0], %1;"
                    :: "r"(hb_rem + (uint32_t)(nb * 128 + ju) * 4), "f"(h)
                    : "memory");
            }
        }
        if (gt == 1)
            Hout[((size_t)b * SS + s) * DD + dir * HH + ju] = roundtf(h);
        __syncthreads();   // all local reads of h(t) done before peer unblocked
        if (gt == 0 && t + 1 < SS) {
            asm volatile("mbarrier.arrive.shared::cluster.b64 _, [%0];"
                :: "r"(mb_rem + (uint32_t)nb * 8) : "memory");
        }
    }
    asm volatile("barrier.cluster.arrive.aligned;" ::: "memory");
    asm volatile("barrier.cluster.wait.aligned;" ::: "memory");
}

// =============================================================================
// launch
// =============================================================================
extern "C" void kernel_launch(void* const* d_in, const int* in_sizes, int n_in,
                              void* d_out, int out_size)
{
    const float* x     = (const float*)d_in[0];
    const float* fwWih = (const float*)d_in[1];
    const float* fwWhh = (const float*)d_in[2];
    const float* fwbih = (const float*)d_in[3];
    const float* fwbhh = (const float*)d_in[4];
    const float* bwWih = (const float*)d_in[5];
    const float* bwWhh = (const float*)d_in[6];
    const float* bwbih = (const float*)d_in[7];
    const float* bwbhh = (const float*)d_in[8];
    const float* Wq    = (const float*)d_in[9];
    const float* Wk    = (const float*)d_in[10];
    const float* Wv    = (const float*)d_in[11];
    float* out = (float*)d_out;

    float *xg, *h, *qk, *v, *sc, *fac, *wqk, *wih, *b1s, *b2s;
    float2 *part;
    cudaGetSymbolAddress((void**)&xg,   g_xg);
    cudaGetSymbolAddress((void**)&h,    g_h);
    cudaGetSymbolAddress((void**)&qk,   g_qk);
    cudaGetSymbolAddress((void**)&v,    g_v);
    cudaGetSymbolAddress((void**)&sc,   g_sc);
    cudaGetSymbolAddress((void**)&part, g_part);
    cudaGetSymbolAddress((void**)&fac,  g_fac);
    cudaGetSymbolAddress((void**)&wqk,  g_wqk);
    cudaGetSymbolAddress((void**)&wih,  g_wih);
    cudaGetSymbolAddress((void**)&b1s,  g_b1);
    cudaGetSymbolAddress((void**)&b2s,  g_b2);

    cudaFuncSetAttribute(mma_gemm_nt<true, true, false, false, false>,
                         cudaFuncAttributeMaxDynamicSharedMemorySize, GEMM_SMEM);
    cudaFuncSetAttribute(mma_gemm_nt<false, true, true, false, false>,
                         cudaFuncAttributeMaxDynamicSharedMemorySize, GEMM_SMEM);
    cudaFuncSetAttribute(mma_gemm_nt<true, false, true, false, false>,
                         cudaFuncAttributeMaxDynamicSharedMemorySize, GEMM_SMEM);
    cudaFuncSetAttribute(mma_gemm_nt<false, false, false, true, false>,
                         cudaFuncAttributeMaxDynamicSharedMemorySize, GEMM_SMEM);
    cudaFuncSetAttribute(mma_gemm_nt<false, false, false, false, true>,
                         cudaFuncAttributeMaxDynamicSharedMemorySize, GEMM_SMEM);

    const long long SD  = (long long)SS * DD;
    const long long SS2 = (long long)SS * SS;
    const long long BSD = (long long)BB * SS * DD;
    const long long WIH = (long long)4 * HH * II;

    cudaMemcpyAsync(wqk,           Wq,    sizeof(float) * DD * DD,
                    cudaMemcpyDeviceToDevice);
    cudaMemcpyAsync(wqk + DD * DD, Wk,    sizeof(float) * DD * DD,
                    cudaMemcpyDeviceToDevice);
    cudaMemcpyAsync(wih,           fwWih, sizeof(float) * WIH,
                    cudaMemcpyDeviceToDevice);
    cudaMemcpyAsync(wih + WIH,     bwWih, sizeof(float) * WIH,
                    cudaMemcpyDeviceToDevice);
    cudaMemcpyAsync(b1s,           fwbih, sizeof(float) * 4 * HH,
                    cudaMemcpyDeviceToDevice);
    cudaMemcpyAsync(b1s + 4 * HH,  bwbih, sizeof(float) * 4 * HH,
                    cudaMemcpyDeviceToDevice);
    cudaMemcpyAsync(b2s,           fwbhh, sizeof(float) * 4 * HH,
                    cudaMemcpyDeviceToDevice);
    cudaMemcpyAsync(b2s + 4 * HH,  bwbhh, sizeof(float) * 4 * HH,
                    cudaMemcpyDeviceToDevice);

    // 1) xg[dir] = x @ Wih[dir]^T + biases (merged fw/bw)
    mma_gemm_nt<true, true, false, false, false>
        <<<dim3(4, 256, 2), 256, GEMM_SMEM>>>(
        x, 0, wih, WIH, xg, (long long)BB * SS * 4 * HH,
        II, 4 * HH, 1.f, b1s, b2s, 4 * HH, nullptr, nullptr);

    // 2) bidirectional LSTM recurrence -> h [B,S,2H]  (64 clusters x 2 CTAs)
    lstm_kernel<<<128, 256>>>(xg, fwWhh, bwWhh, h);

    // 3) q,k projections merged (z=2)
    mma_gemm_nt<false, true, true, false, false>
        <<<dim3(2, 256, 2), 256, GEMM_SMEM>>>(
        h, 0, wqk, (long long)DD * DD, qk, BSD, DD, DD, 1.f,
        nullptr, nullptr, 0, nullptr, nullptr);

    // 3b) vT = Wv @ h^T
    mma_gemm_nt<true, false, true, false, false>
        <<<dim3(8, 2, 32), 256, GEMM_SMEM>>>(
        Wv, 0, h, SD, v, SD, DD, SS, 1.f, nullptr, nullptr, 0,
        nullptr, nullptr);

    // 4) scores: C = exp(q@k^T/16 - m_tile), partials (m_tile, s_tile)
    mma_gemm_nt<false, false, false, true, false>
        <<<dim3(8, 8, 32), 256, GEMM_SMEM>>>(
        qk, SD, qk + BSD, SD, sc, SS2, DD, SS, 0.0625f,
        nullptr, nullptr, 0, part, nullptr);

    // 5) combine partials -> per-(row, tile) factors
    softmax_combine<<<BB * SS / 256, 256>>>(part, fac);

    // 6) out = (exp-values * fac) @ vT^T   (flash-style factored softmax)
    mma_gemm_nt<false, false, false, false, true>
        <<<dim3(2, 8, 32), 256, GEMM_SMEM>>>(
        sc, SS2, v, SD, out, SD, SS, DD, 1.f,
        nullptr, nullptr, 0, nullptr, fac);
}